// round 12
// baseline (speedup 1.0000x reference)
#include <cuda_runtime.h>
#include <math.h>
#include <cstdint>

#define C_CH 128
#define VN 10
#define NB_TOT 32768
#define R_TOT (NB_TOT * VN)     // 327680 rows
#define N3 384
#define HEADS 8
#define DH 16
#define BN_EPS 1e-5f

#define STATS_BLOCKS 512
#define ROWS_PER_STAT (R_TOT / STATS_BLOCKS)

#define BPC 6
#define MROWS (BPC * VN)        // 60 valid rows, padded to 64
#define THREADS 256
#define GRID_MAIN ((NB_TOT + BPC - 1) / BPC)   // 5462

// smem layout (byte offsets)
#define XS_OFF    0u            // A-pack: 8192 floats = 32768 B (x tile, later P)
#define WT_OFF    32768u        // 2 x 32KB packed weight strips
#define WT_BUF_B  32768u
#define QKV_OFF   98304u        // [64][388] floats = 99328 B
#define BIAS1_OFF 197632u       // 384 f
#define BOUT_OFF  199168u       // 128 f
#define MASK_OFF  199680u       // 100 f
#define SMEM_TOTAL 200192u

// ---------------- device scratch ----------------
__device__ float g_psum[STATS_BLOCKS][C_CH];
__device__ float g_psumsq[STATS_BLOCKS][C_CH];
__device__ float g_a[C_CH];
__device__ float g_b[C_CH];
__device__ float g_bias1[N3];
__device__ float g_w1p[3 * 16384];   // fragment-packed folded W1 (per chunk: 2 strips x 8192 floats)
__device__ float g_w2p[16384];       // fragment-packed W2

// ---------------- helpers ----------------
__device__ __forceinline__ uint32_t smem_u32(const void* p) {
    uint32_t a;
    asm("{ .reg .u64 t; cvta.to.shared.u64 t, %1; cvt.u32.u64 %0, t; }" : "=r"(a) : "l"(p));
    return a;
}
__device__ __forceinline__ float tf32_round(float f) {
    uint32_t r;
    asm("cvt.rna.tf32.f32 %0, %1;" : "=r"(r) : "f"(f));
    return __uint_as_float(r);
}
#define CP_ASYNC16(dst, src) \
    asm volatile("cp.async.ca.shared.global [%0], [%1], 16;" :: "r"(dst), "l"(src) : "memory")
#define CP_COMMIT() asm volatile("cp.async.commit_group;" ::: "memory")
#define CP_WAIT(n)  asm volatile("cp.async.wait_group %0;" :: "n"(n) : "memory")

__device__ __forceinline__ void mma8(float* d, const float4& a, uint32_t b0, uint32_t b1) {
    asm volatile(
        "mma.sync.aligned.m16n8k8.row.col.f32.tf32.tf32.f32 "
        "{%0,%1,%2,%3},{%4,%5,%6,%7},{%8,%9},{%0,%1,%2,%3};"
        : "+f"(d[0]), "+f"(d[1]), "+f"(d[2]), "+f"(d[3])
        : "r"(__float_as_uint(a.x)), "r"(__float_as_uint(a.y)),
          "r"(__float_as_uint(a.z)), "r"(__float_as_uint(a.w)),
          "r"(b0), "r"(b1));
}

// B-pack float index: strip-local. k in [0,127] (within chunk), n in [0,127].
__device__ __forceinline__ int bpack_idx(int k, int n) {
    const int s = k >> 6, kr = k & 63;
    const int ks = kr >> 3, t = kr & 7, koff = t >> 2, tig = t & 3;
    const int wn = n >> 5, nr = n & 31, nt = nr >> 3, g = nr & 7;
    const int lane = g * 4 + tig;
    return s * 8192 + (((wn * 8 + ks) * 2 + koff) * 32 + lane) * 4 + nt;
}
// A-pack float index: m in [0,63] row, col in [0,127] k.
__device__ __forceinline__ int apack_idx(int m, int col) {
    const int wm = m >> 5, mr = m & 31;
    const int mt = mr >> 4, i = (mr >> 3) & 1, g = mr & 7;
    const int kk = col >> 3, t = col & 7, koff = t >> 2, tig = t & 3;
    const int lane = g * 4 + tig;
    return (((wm * 16 + kk) * 2 + mt) * 32 + lane) * 4 + (i + 2 * koff);
}

// ---------------- kernel 1: BN partial stats ----------------
__global__ __launch_bounds__(128)
void ga_stats_kernel(const float* __restrict__ x) {
    const int c = threadIdx.x;
    const float* p = x + (size_t)blockIdx.x * ROWS_PER_STAT * C_CH + c;
    float s = 0.f, s2 = 0.f;
#pragma unroll 8
    for (int r = 0; r < ROWS_PER_STAT; ++r) {
        float v = p[(size_t)r * C_CH];
        s += v;
        s2 = fmaf(v, v, s2);
    }
    g_psum[blockIdx.x][c] = s;
    g_psumsq[blockIdx.x][c] = s2;
}

// ---------------- kernel 2: finalize stats ----------------
__global__ __launch_bounds__(128)
void ga_prep_kernel(const float* __restrict__ gamma, const float* __restrict__ beta) {
    const int c = threadIdx.x;
    float s = 0.f, s2 = 0.f;
    for (int b = 0; b < STATS_BLOCKS; ++b) { s += g_psum[b][c]; s2 += g_psumsq[b][c]; }
    const float invR = 1.0f / (float)R_TOT;
    float mean = s * invR;
    float var = s2 * invR - mean * mean;
    float rstd = rsqrtf(var + BN_EPS);
    float a = gamma[c] * rstd;
    g_a[c] = a;
    g_b[c] = beta[c] - mean * a;
}

// ---------------- kernel 3: fold W1 (BN-folded) + W2 into packed layouts + bias1 ----
// blocks 0..383: W1 column n3; blocks 384..511: W2 k-row (blockIdx-384)
__global__ __launch_bounds__(128)
void ga_fold_kernel(const float* __restrict__ w_qkv, const float* __restrict__ w_out) {
    if (blockIdx.x < N3) {
        const int n3 = blockIdx.x;
        const int k = threadIdx.x;
        float wv = w_qkv[(size_t)k * N3 + n3];
        const int chunk = n3 >> 7, n = n3 & 127;
        g_w1p[chunk * 16384 + bpack_idx(k, n)] = tf32_round(g_a[k] * wv);
        __shared__ float red[128];
        red[k] = g_b[k] * wv;
        __syncthreads();
        for (int off = 64; off > 0; off >>= 1) {
            if (k < off) red[k] += red[k + off];
            __syncthreads();
        }
        if (k == 0) g_bias1[n3] = red[0];
    } else {
        const int k = blockIdx.x - N3;   // 0..127
        const int n = threadIdx.x;       // 0..127
        g_w2p[bpack_idx(k, n)] = tf32_round(w_out[(size_t)k * C_CH + n]);
    }
}

// ---------------- main fused kernel ----------------
__device__ __forceinline__ void issue_strip(int s, char* smem, int tid) {
    const float* src = (s < 6) ? (g_w1p + (s >> 1) * 16384 + (s & 1) * 8192)
                               : (g_w2p + (s & 1) * 8192);
    const uint32_t dstbase = smem_u32(smem + WT_OFF + (uint32_t)(s & 1) * WT_BUF_B);
#pragma unroll
    for (int j = 0; j < 8; ++j) {
        const int u = tid + j * THREADS;          // 2048 units of 16B (32KB strip)
        CP_ASYNC16(dstbase + (uint32_t)u * 16u, src + u * 4);
    }
}

__device__ __forceinline__ void compute_half(
    const float4* __restrict__ xp, const float4* __restrict__ wp,
    int h, int wm, int wn, int lane, float acc[2][4][4])
{
#pragma unroll
    for (int ks = 0; ks < 8; ++ks) {
        const int kk = h * 8 + ks;
        const float4 a0 = xp[((wm * 16 + kk) * 2 + 0) * 32 + lane];
        const float4 a1 = xp[((wm * 16 + kk) * 2 + 1) * 32 + lane];
        const float4 b0 = wp[((wn * 8 + ks) * 2 + 0) * 32 + lane];
        const float4 b1 = wp[((wn * 8 + ks) * 2 + 1) * 32 + lane];
        mma8(acc[0][0], a0, __float_as_uint(b0.x), __float_as_uint(b1.x));
        mma8(acc[0][1], a0, __float_as_uint(b0.y), __float_as_uint(b1.y));
        mma8(acc[0][2], a0, __float_as_uint(b0.z), __float_as_uint(b1.z));
        mma8(acc[0][3], a0, __float_as_uint(b0.w), __float_as_uint(b1.w));
        mma8(acc[1][0], a1, __float_as_uint(b0.x), __float_as_uint(b1.x));
        mma8(acc[1][1], a1, __float_as_uint(b0.y), __float_as_uint(b1.y));
        mma8(acc[1][2], a1, __float_as_uint(b0.z), __float_as_uint(b1.z));
        mma8(acc[1][3], a1, __float_as_uint(b0.w), __float_as_uint(b1.w));
    }
}

__global__ __launch_bounds__(THREADS, 1)
void ga_main_kernel(const float* __restrict__ x,
                    const float* __restrict__ b_out,
                    const float* __restrict__ mask,
                    float* __restrict__ out)
{
    extern __shared__ char smem[];
    float* xs = (float*)(smem + XS_OFF);
    float* qkv = (float*)(smem + QKV_OFF);
    float* bias1s = (float*)(smem + BIAS1_OFF);
    float* bouts = (float*)(smem + BOUT_OFF);
    float* mk = (float*)(smem + MASK_OFF);
    const float4* xp = (const float4*)(smem + XS_OFF);
    const float4* wp0 = (const float4*)(smem + WT_OFF);
    const float4* wp1 = (const float4*)(smem + WT_OFF + WT_BUF_B);

    const int tid = threadIdx.x;
    const int lane = tid & 31;
    const int wid = tid >> 5;
    const int wm = wid & 1;        // 2 M-strips of 32
    const int wn = wid >> 1;       // 4 N-strips of 32
    const int g = lane >> 2;
    const int tig = lane & 3;

    const int row0 = blockIdx.x * MROWS;
    const int valid_rows = min(MROWS, R_TOT - row0);
    const int valid_items = min(BPC, NB_TOT - blockIdx.x * BPC);

    // prefetch weight strips 0,1 (gemm1 chunk0)
    issue_strip(0, smem, tid); CP_COMMIT();
    issue_strip(1, smem, tid); CP_COMMIT();

    // constants
    for (int e = tid; e < N3; e += THREADS) bias1s[e] = g_bias1[e];
    for (int e = tid; e < C_CH; e += THREADS) bouts[e] = b_out[e];
    for (int e = tid; e < VN * VN; e += THREADS) mk[e] = mask[e];

    // x tile -> xs A-pack (tf32-rounded), pad rows zeroed
    {
        const float4* xv = reinterpret_cast<const float4*>(x);
#pragma unroll
        for (int j = 0; j < 8; ++j) {
            const int idx = tid + j * THREADS;       // 2048 = 64 rows x 32 col-groups
            const int m = idx >> 5, gq = idx & 31;
            float4 v = make_float4(0.f, 0.f, 0.f, 0.f);
            if (m < valid_rows) v = xv[(size_t)(row0 + m) * 32 + gq];
            // pack: col = gq*4 + cc
            const int wmL = m >> 5, mr = m & 31;
            const int mt = mr >> 4, iL = (mr >> 3) & 1, gL = mr & 7;
            const int kk = gq >> 1, koff = gq & 1;
            const int base = (((wmL * 16 + kk) * 2 + mt) * 32 + gL * 4) * 4 + (iL + 2 * koff);
            xs[base + 0 * 4] = tf32_round(v.x);
            xs[base + 1 * 4] = tf32_round(v.y);
            xs[base + 2 * 4] = tf32_round(v.z);
            xs[base + 3 * 4] = tf32_round(v.w);
        }
    }
    __syncthreads();

    // ---- GEMM1: qkv = x @ W1' + bias1, 3 N-chunks of 128 ----
#pragma unroll 1
    for (int c = 0; c < 3; ++c) {
        float acc[2][4][4];
#pragma unroll
        for (int nt = 0; nt < 4; ++nt) {
            const int col = c * 128 + wn * 32 + nt * 8 + tig * 2;
            const float bz0 = bias1s[col], bz1 = bias1s[col + 1];
#pragma unroll
            for (int mt = 0; mt < 2; ++mt) {
                acc[mt][nt][0] = bz0; acc[mt][nt][1] = bz1;
                acc[mt][nt][2] = bz0; acc[mt][nt][3] = bz1;
            }
        }
#pragma unroll 1
        for (int h = 0; h < 2; ++h) {
            const int s = c * 2 + h;
            CP_WAIT(1);
            __syncthreads();
            compute_half(xp, (s & 1) ? wp1 : wp0, h, wm, wn, lane, acc);
            __syncthreads();
            issue_strip(s + 2, smem, tid); CP_COMMIT();
        }
        // store acc -> qkv (row-major, stride 388)
#pragma unroll
        for (int mt = 0; mt < 2; ++mt) {
            const int row = wm * 32 + mt * 16 + g;
#pragma unroll
            for (int nt = 0; nt < 4; ++nt) {
                const int col = c * 128 + wn * 32 + nt * 8 + tig * 2;
                *reinterpret_cast<float2*>(&qkv[row * 388 + col]) =
                    make_float2(acc[mt][nt][0], acc[mt][nt][1]);
                *reinterpret_cast<float2*>(&qkv[(row + 8) * 388 + col]) =
                    make_float2(acc[mt][nt][2], acc[mt][nt][3]);
            }
        }
    }
    __syncthreads();

    // ---- attention (fp32, vectorized loads); writes P (tf32) into xs A-pack ----
    for (int it = tid; it < BPC * HEADS * VN; it += THREADS) {
        const int b = it / (HEADS * VN);
        const int rem = it - b * (HEADS * VN);
        const int h = rem / VN;
        const int i = rem - h * VN;
        if (b < valid_items) {
            const int h16 = h * DH;
            const int ri = b * VN + i;
            float4 q0 = *(const float4*)&qkv[ri * 388 + h16];
            float4 q1 = *(const float4*)&qkv[ri * 388 + h16 + 4];
            float4 q2 = *(const float4*)&qkv[ri * 388 + h16 + 8];
            float4 q3 = *(const float4*)&qkv[ri * 388 + h16 + 12];
            float dots[VN];
            float mx = -1e30f;
#pragma unroll
            for (int j = 0; j < VN; ++j) {
                const float* kr = &qkv[(b * VN + j) * 388 + 128 + h16];
                float4 k0 = *(const float4*)(kr);
                float4 k1 = *(const float4*)(kr + 4);
                float4 k2 = *(const float4*)(kr + 8);
                float4 k3 = *(const float4*)(kr + 12);
                float s = q0.x * k0.x + q0.y * k0.y + q0.z * k0.z + q0.w * k0.w;
                s = fmaf(q1.x, k1.x, s); s = fmaf(q1.y, k1.y, s);
                s = fmaf(q1.z, k1.z, s); s = fmaf(q1.w, k1.w, s);
                s = fmaf(q2.x, k2.x, s); s = fmaf(q2.y, k2.y, s);
                s = fmaf(q2.z, k2.z, s); s = fmaf(q2.w, k2.w, s);
                s = fmaf(q3.x, k3.x, s); s = fmaf(q3.y, k3.y, s);
                s = fmaf(q3.z, k3.z, s); s = fmaf(q3.w, k3.w, s);
                float v = s * 0.25f * mk[i * VN + j];
                dots[j] = v;
                mx = fmaxf(mx, v);
            }
            float ssum = 0.f;
#pragma unroll
            for (int j = 0; j < VN; ++j) { dots[j] = __expf(dots[j] - mx); ssum += dots[j]; }
            const float inv = 1.0f / ssum;
            float o[DH];
#pragma unroll
            for (int d = 0; d < DH; ++d) o[d] = 0.f;
#pragma unroll
            for (int j = 0; j < VN; ++j) {
                const float* vr = &qkv[(b * VN + j) * 388 + 256 + h16];
                const float w = dots[j];
                float4 v0 = *(const float4*)(vr);
                float4 v1 = *(const float4*)(vr + 4);
                float4 v2 = *(const float4*)(vr + 8);
                float4 v3 = *(const float4*)(vr + 12);
                o[0] = fmaf(w, v0.x, o[0]);  o[1] = fmaf(w, v0.y, o[1]);
                o[2] = fmaf(w, v0.z, o[2]);  o[3] = fmaf(w, v0.w, o[3]);
                o[4] = fmaf(w, v1.x, o[4]);  o[5] = fmaf(w, v1.y, o[5]);
                o[6] = fmaf(w, v1.z, o[6]);  o[7] = fmaf(w, v1.w, o[7]);
                o[8] = fmaf(w, v2.x, o[8]);  o[9] = fmaf(w, v2.y, o[9]);
                o[10] = fmaf(w, v2.z, o[10]); o[11] = fmaf(w, v2.w, o[11]);
                o[12] = fmaf(w, v3.x, o[12]); o[13] = fmaf(w, v3.y, o[13]);
                o[14] = fmaf(w, v3.z, o[14]); o[15] = fmaf(w, v3.w, o[15]);
            }
#pragma unroll
            for (int d = 0; d < DH; ++d)
                xs[apack_idx(ri, h16 + d)] = tf32_round(o[d] * inv);
        }
    }
    __syncthreads();

    // ---- GEMM2: out = P @ W2 + b_out (W2 strips 6,7 already prefetched) ----
    CP_WAIT(0);
    __syncthreads();
    {
        float acc[2][4][4];
#pragma unroll
        for (int nt = 0; nt < 4; ++nt) {
            const int col = wn * 32 + nt * 8 + tig * 2;
            const float bz0 = bouts[col], bz1 = bouts[col + 1];
#pragma unroll
            for (int mt = 0; mt < 2; ++mt) {
                acc[mt][nt][0] = bz0; acc[mt][nt][1] = bz1;
                acc[mt][nt][2] = bz0; acc[mt][nt][3] = bz1;
            }
        }
        compute_half(xp, wp0, 0, wm, wn, lane, acc);
        compute_half(xp, wp1, 1, wm, wn, lane, acc);

#pragma unroll
        for (int mt = 0; mt < 2; ++mt) {
            const int row = wm * 32 + mt * 16 + g;
#pragma unroll
            for (int nt = 0; nt < 4; ++nt) {
                const int col = wn * 32 + nt * 8 + tig * 2;
                if (row < valid_rows) {
                    float2 v = make_float2(acc[mt][nt][0], acc[mt][nt][1]);
                    *reinterpret_cast<float2*>(&out[(size_t)(row0 + row) * C_CH + col]) = v;
                }
                if (row + 8 < valid_rows) {
                    float2 v = make_float2(acc[mt][nt][2], acc[mt][nt][3]);
                    *reinterpret_cast<float2*>(&out[(size_t)(row0 + row + 8) * C_CH + col]) = v;
                }
            }
        }
    }
}

// ---------------- launch ----------------
extern "C" void kernel_launch(void* const* d_in, const int* in_sizes, int n_in,
                              void* d_out, int out_size) {
    (void)in_sizes; (void)n_in; (void)out_size;
    const float* x     = (const float*)d_in[0];
    const float* gamma = (const float*)d_in[1];
    const float* beta  = (const float*)d_in[2];
    const float* w_qkv = (const float*)d_in[3];
    const float* w_out = (const float*)d_in[4];
    const float* b_out = (const float*)d_in[5];
    const float* mask  = (const float*)d_in[6];
    float* out = (float*)d_out;

    cudaFuncSetAttribute(ga_main_kernel,
                         cudaFuncAttributeMaxDynamicSharedMemorySize,
                         (int)SMEM_TOTAL);

    ga_stats_kernel<<<STATS_BLOCKS, 128>>>(x);
    ga_prep_kernel<<<1, 128>>>(gamma, beta);
    ga_fold_kernel<<<N3 + C_CH, 128>>>(w_qkv, w_out);
    ga_main_kernel<<<GRID_MAIN, THREADS, SMEM_TOTAL>>>(x, b_out, mask, out);
}

// round 13
// speedup vs baseline: 1.8883x; 1.8883x over previous
#include <cuda_runtime.h>
#include <cuda_fp16.h>
#include <math.h>
#include <cstdint>

#define C_CH 128
#define VN 10
#define NB_TOT 32768
#define R_TOT (NB_TOT * VN)     // 327680 rows
#define N3 384
#define HEADS 8
#define DH 16
#define BN_EPS 1e-5f

#define STATS_BLOCKS 512
#define ROWS_PER_STAT (R_TOT / STATS_BLOCKS)

#define BPC 6
#define MROWS (BPC * VN)        // 60 valid rows, padded to 64
#define THREADS 256
#define GRID_MAIN ((NB_TOT + BPC - 1) / BPC)   // 5462

// smem layout (byte offsets) — total ~99.4KB -> 2 CTAs/SM
#define XS_OFF    0u            // A-pack fp16: 16384 B (x tile, later P)
#define WT_OFF    16384u        // 2 x 16KB packed fp16 weight strips
#define WT_BUF_B  16384u
#define QKV_OFF   49152u        // [64][392] halves = 50176 B
#define QKV_STR   392
#define BIAS1_OFF 99328u        // 384 f32
#define BOUT_OFF  100864u       // 128 f32
#define MASK_OFF  101376u       // 100 f32
#define SMEM_TOTAL 101888u

// ---------------- device scratch ----------------
__device__ float g_psum[STATS_BLOCKS][C_CH];
__device__ float g_psumsq[STATS_BLOCKS][C_CH];
__device__ float g_a[C_CH];
__device__ float g_b[C_CH];
__device__ float g_bias1[N3];
__device__ __half g_w1h[3 * 16384];  // fragment-packed fp16 folded W1 (chunk = 2 strips x 8192 halves)
__device__ __half g_w2h[16384];      // fragment-packed fp16 W2

// ---------------- helpers ----------------
__device__ __forceinline__ uint32_t smem_u32(const void* p) {
    uint32_t a;
    asm("{ .reg .u64 t; cvta.to.shared.u64 t, %1; cvt.u32.u64 %0, t; }" : "=r"(a) : "l"(p));
    return a;
}
#define CP_ASYNC16(dst, src) \
    asm volatile("cp.async.ca.shared.global [%0], [%1], 16;" :: "r"(dst), "l"(src) : "memory")
#define CP_COMMIT() asm volatile("cp.async.commit_group;" ::: "memory")
#define CP_WAIT(n)  asm volatile("cp.async.wait_group %0;" :: "n"(n) : "memory")

// fp16 MMA, fp32 accumulate: m16n8k16
__device__ __forceinline__ void mma16(float* d, const float4& a, uint32_t b0, uint32_t b1) {
    asm volatile(
        "mma.sync.aligned.m16n8k16.row.col.f32.f16.f16.f32 "
        "{%0,%1,%2,%3},{%4,%5,%6,%7},{%8,%9},{%0,%1,%2,%3};"
        : "+f"(d[0]), "+f"(d[1]), "+f"(d[2]), "+f"(d[3])
        : "r"(__float_as_uint(a.x)), "r"(__float_as_uint(a.y)),
          "r"(__float_as_uint(a.z)), "r"(__float_as_uint(a.w)),
          "r"(b0), "r"(b1));
}

// W-pack half index within one chunk (k in [0,128), n in [0,128))
__device__ __forceinline__ int wpack_h_idx(int k, int n) {
    const int ksg = k >> 4;
    const int strip = ksg >> 2, kks = ksg & 3;
    const int k_in = k & 15, kh = k_in >> 3, klo = k_in & 1, t = (k_in >> 1) & 3;
    const int wn = n >> 5, nr = n & 31, nt = nr >> 3, g = nr & 7;
    const int unit = ((wn * 4 + kks) * 2 + kh) * 32 + g * 4 + t;
    return strip * 8192 + unit * 8 + nt * 2 + klo;
}

// load 8 consecutive halves (16B aligned) -> 8 floats
__device__ __forceinline__ void ld8(const __half* p, float* f) {
    float4 r = *reinterpret_cast<const float4*>(p);
    uint32_t u0 = __float_as_uint(r.x), u1 = __float_as_uint(r.y);
    uint32_t u2 = __float_as_uint(r.z), u3 = __float_as_uint(r.w);
    float2 f0 = __half22float2(*reinterpret_cast<__half2*>(&u0));
    float2 f1 = __half22float2(*reinterpret_cast<__half2*>(&u1));
    float2 f2 = __half22float2(*reinterpret_cast<__half2*>(&u2));
    float2 f3 = __half22float2(*reinterpret_cast<__half2*>(&u3));
    f[0] = f0.x; f[1] = f0.y; f[2] = f1.x; f[3] = f1.y;
    f[4] = f2.x; f[5] = f2.y; f[6] = f3.x; f[7] = f3.y;
}

// ---------------- kernel 1: BN partial stats ----------------
__global__ __launch_bounds__(128)
void ga_stats_kernel(const float* __restrict__ x) {
    const int c = threadIdx.x;
    const float* p = x + (size_t)blockIdx.x * ROWS_PER_STAT * C_CH + c;
    float s = 0.f, s2 = 0.f;
#pragma unroll 8
    for (int r = 0; r < ROWS_PER_STAT; ++r) {
        float v = p[(size_t)r * C_CH];
        s += v;
        s2 = fmaf(v, v, s2);
    }
    g_psum[blockIdx.x][c] = s;
    g_psumsq[blockIdx.x][c] = s2;
}

// ---------------- kernel 2: finalize stats ----------------
__global__ __launch_bounds__(128)
void ga_prep_kernel(const float* __restrict__ gamma, const float* __restrict__ beta) {
    const int c = threadIdx.x;
    float s = 0.f, s2 = 0.f;
    for (int b = 0; b < STATS_BLOCKS; ++b) { s += g_psum[b][c]; s2 += g_psumsq[b][c]; }
    const float invR = 1.0f / (float)R_TOT;
    float mean = s * invR;
    float var = s2 * invR - mean * mean;
    float rstd = rsqrtf(var + BN_EPS);
    float a = gamma[c] * rstd;
    g_a[c] = a;
    g_b[c] = beta[c] - mean * a;
}

// ---------------- kernel 3: fold W1 (BN) + W2 into packed fp16 layouts + bias1 ----
__global__ __launch_bounds__(128)
void ga_fold_kernel(const float* __restrict__ w_qkv, const float* __restrict__ w_out) {
    if (blockIdx.x < N3) {
        const int n3 = blockIdx.x;
        const int k = threadIdx.x;
        float wv = w_qkv[(size_t)k * N3 + n3];
        const int chunk = n3 >> 7, n = n3 & 127;
        g_w1h[chunk * 16384 + wpack_h_idx(k, n)] = __float2half_rn(g_a[k] * wv);
        __shared__ float red[128];
        red[k] = g_b[k] * wv;
        __syncthreads();
        for (int off = 64; off > 0; off >>= 1) {
            if (k < off) red[k] += red[k + off];
            __syncthreads();
        }
        if (k == 0) g_bias1[n3] = red[0];
    } else {
        const int k = blockIdx.x - N3;   // 0..127
        const int n = threadIdx.x;       // 0..127
        g_w2h[wpack_h_idx(k, n)] = __float2half_rn(w_out[(size_t)k * C_CH + n]);
    }
}

// ---------------- main fused kernel ----------------
__device__ __forceinline__ void issue_strip(int s, char* smem, int tid) {
    const __half* src = (s < 6) ? (g_w1h + (s >> 1) * 16384 + (s & 1) * 8192)
                                : (g_w2h + (s & 1) * 8192);
    const uint32_t dstbase = smem_u32(smem + WT_OFF + (uint32_t)(s & 1) * WT_BUF_B);
#pragma unroll
    for (int j = 0; j < 4; ++j) {
        const int u = tid + j * THREADS;          // 1024 units of 16B (16KB strip)
        CP_ASYNC16(dstbase + (uint32_t)u * 16u, src + u * 8);
    }
}

__device__ __forceinline__ void compute_half(
    const float4* __restrict__ xp, const float4* __restrict__ wp,
    int h, int wm, int wn, int lane, float acc[2][4][4])
{
#pragma unroll
    for (int kks = 0; kks < 4; ++kks) {
        const int kk = h * 4 + kks;
        const float4 a0 = xp[((wm * 8 + kk) * 2 + 0) * 32 + lane];
        const float4 a1 = xp[((wm * 8 + kk) * 2 + 1) * 32 + lane];
        const float4 blo = wp[((wn * 4 + kks) * 2 + 0) * 32 + lane];
        const float4 bhi = wp[((wn * 4 + kks) * 2 + 1) * 32 + lane];
        mma16(acc[0][0], a0, __float_as_uint(blo.x), __float_as_uint(bhi.x));
        mma16(acc[0][1], a0, __float_as_uint(blo.y), __float_as_uint(bhi.y));
        mma16(acc[0][2], a0, __float_as_uint(blo.z), __float_as_uint(bhi.z));
        mma16(acc[0][3], a0, __float_as_uint(blo.w), __float_as_uint(bhi.w));
        mma16(acc[1][0], a1, __float_as_uint(blo.x), __float_as_uint(bhi.x));
        mma16(acc[1][1], a1, __float_as_uint(blo.y), __float_as_uint(bhi.y));
        mma16(acc[1][2], a1, __float_as_uint(blo.z), __float_as_uint(bhi.z));
        mma16(acc[1][3], a1, __float_as_uint(blo.w), __float_as_uint(bhi.w));
    }
}

__global__ __launch_bounds__(THREADS, 2)
void ga_main_kernel(const float* __restrict__ x,
                    const float* __restrict__ b_out,
                    const float* __restrict__ mask,
                    float* __restrict__ out)
{
    extern __shared__ char smem[];
    __half* xsh = (__half*)(smem + XS_OFF);
    __half* qkvh = (__half*)(smem + QKV_OFF);
    float* bias1s = (float*)(smem + BIAS1_OFF);
    float* bouts = (float*)(smem + BOUT_OFF);
    float* mk = (float*)(smem + MASK_OFF);
    const float4* xp = (const float4*)(smem + XS_OFF);
    const float4* wp0 = (const float4*)(smem + WT_OFF);
    const float4* wp1 = (const float4*)(smem + WT_OFF + WT_BUF_B);

    const int tid = threadIdx.x;
    const int lane = tid & 31;
    const int wid = tid >> 5;
    const int wm = wid & 1;        // 2 M-strips of 32
    const int wn = wid >> 1;       // 4 N-strips of 32
    const int g = lane >> 2;
    const int tig = lane & 3;

    const int row0 = blockIdx.x * MROWS;
    const int valid_rows = min(MROWS, R_TOT - row0);
    const int valid_items = min(BPC, NB_TOT - blockIdx.x * BPC);

    // prefetch weight strips 0,1 (gemm1 chunk0)
    issue_strip(0, smem, tid); CP_COMMIT();
    issue_strip(1, smem, tid); CP_COMMIT();

    // constants
    for (int e = tid; e < N3; e += THREADS) bias1s[e] = g_bias1[e];
    for (int e = tid; e < C_CH; e += THREADS) bouts[e] = b_out[e];
    for (int e = tid; e < VN * VN; e += THREADS) mk[e] = mask[e];

    // x tile -> xs A-pack (fp16), pad rows zeroed
    {
        const float4* xv = reinterpret_cast<const float4*>(x);
#pragma unroll
        for (int j = 0; j < 8; ++j) {
            const int idx = tid + j * THREADS;       // 2048 = 64 rows x 32 col-groups
            const int m = idx >> 5, gq = idx & 31;
            float4 v = make_float4(0.f, 0.f, 0.f, 0.f);
            if (m < valid_rows) v = xv[(size_t)(row0 + m) * 32 + gq];
            const int wmL = m >> 5, rin = m & 31;
            const int mt = rin >> 4, r16 = rin & 15;
            const int gL = r16 & 7, iL = r16 >> 3;
            const int col0 = gq * 4;
            const int kk = col0 >> 4;
            const int k_in0 = col0 & 15;
            const int khi = k_in0 >> 3;
            const int t0 = (k_in0 >> 1) & 3;          // even; pair2 -> t0+1
            const int r = iL + 2 * khi;
            const int ubase = ((wmL * 8 + kk) * 2 + mt) * 32 + gL * 4;
            *reinterpret_cast<__half2*>(xsh + (ubase + t0) * 8 + r * 2) =
                __floats2half2_rn(v.x, v.y);
            *reinterpret_cast<__half2*>(xsh + (ubase + t0 + 1) * 8 + r * 2) =
                __floats2half2_rn(v.z, v.w);
        }
    }
    __syncthreads();

    // ---- GEMM1: qkv = x @ W1' + bias1, 3 N-chunks of 128 ----
#pragma unroll 1
    for (int c = 0; c < 3; ++c) {
        float acc[2][4][4];
#pragma unroll
        for (int nt = 0; nt < 4; ++nt) {
            const int col = c * 128 + wn * 32 + nt * 8 + tig * 2;
            const float bz0 = bias1s[col], bz1 = bias1s[col + 1];
#pragma unroll
            for (int mt = 0; mt < 2; ++mt) {
                acc[mt][nt][0] = bz0; acc[mt][nt][1] = bz1;
                acc[mt][nt][2] = bz0; acc[mt][nt][3] = bz1;
            }
        }
#pragma unroll 1
        for (int h = 0; h < 2; ++h) {
            const int s = c * 2 + h;
            CP_WAIT(1);
            __syncthreads();
            compute_half(xp, (s & 1) ? wp1 : wp0, h, wm, wn, lane, acc);
            __syncthreads();
            issue_strip(s + 2, smem, tid); CP_COMMIT();
        }
        // store acc -> qkv (fp16, stride QKV_STR)
#pragma unroll
        for (int mt = 0; mt < 2; ++mt) {
            const int row = wm * 32 + mt * 16 + g;
#pragma unroll
            for (int nt = 0; nt < 4; ++nt) {
                const int col = c * 128 + wn * 32 + nt * 8 + tig * 2;
                *reinterpret_cast<__half2*>(qkvh + row * QKV_STR + col) =
                    __floats2half2_rn(acc[mt][nt][0], acc[mt][nt][1]);
                *reinterpret_cast<__half2*>(qkvh + (row + 8) * QKV_STR + col) =
                    __floats2half2_rn(acc[mt][nt][2], acc[mt][nt][3]);
            }
        }
    }
    __syncthreads();

    // ---- attention (fp32 math, fp16 storage); writes P into xs A-pack ----
    for (int it = tid; it < BPC * HEADS * VN; it += THREADS) {
        const int b = it / (HEADS * VN);
        const int rem = it - b * (HEADS * VN);
        const int h = rem / VN;
        const int i = rem - h * VN;
        if (b < valid_items) {
            const int h16 = h * DH;
            const int ri = b * VN + i;
            float qv[DH];
            ld8(qkvh + ri * QKV_STR + h16, qv);
            ld8(qkvh + ri * QKV_STR + h16 + 8, qv + 8);
            float dots[VN];
            float mx = -1e30f;
#pragma unroll
            for (int j = 0; j < VN; ++j) {
                float kvv[DH];
                const __half* kr = qkvh + (b * VN + j) * QKV_STR + 128 + h16;
                ld8(kr, kvv);
                ld8(kr + 8, kvv + 8);
                float s = 0.f;
#pragma unroll
                for (int d = 0; d < DH; ++d) s = fmaf(qv[d], kvv[d], s);
                float v = s * 0.25f * mk[i * VN + j];
                dots[j] = v;
                mx = fmaxf(mx, v);
            }
            float ssum = 0.f;
#pragma unroll
            for (int j = 0; j < VN; ++j) { dots[j] = __expf(dots[j] - mx); ssum += dots[j]; }
            const float inv = 1.0f / ssum;
            float o[DH];
#pragma unroll
            for (int d = 0; d < DH; ++d) o[d] = 0.f;
#pragma unroll
            for (int j = 0; j < VN; ++j) {
                float vv[DH];
                const __half* vr = qkvh + (b * VN + j) * QKV_STR + 256 + h16;
                ld8(vr, vv);
                ld8(vr + 8, vv + 8);
                const float w = dots[j];
#pragma unroll
                for (int d = 0; d < DH; ++d) o[d] = fmaf(w, vv[d], o[d]);
            }
            // write P into A-pack: row ri, cols h16+d (kk = h)
            const int wmL = ri >> 5, rin = ri & 31;
            const int mt = rin >> 4, r16 = rin & 15;
            const int gL = r16 & 7, iL = r16 >> 3;
            const int ubase = ((wmL * 8 + h) * 2 + mt) * 32 + gL * 4;
#pragma unroll
            for (int d = 0; d < DH; d += 2) {
                const int khi = d >> 3;
                const int t = (d >> 1) & 3;
                const int r = iL + 2 * khi;
                *reinterpret_cast<__half2*>(xsh + (ubase + t) * 8 + r * 2) =
                    __floats2half2_rn(o[d] * inv, o[d + 1] * inv);
            }
        }
    }
    __syncthreads();

    // ---- GEMM2: out = P @ W2 + b_out (W2 strips 6,7 already prefetched) ----
    CP_WAIT(0);
    __syncthreads();
    {
        float acc[2][4][4];
#pragma unroll
        for (int nt = 0; nt < 4; ++nt) {
            const int col = wn * 32 + nt * 8 + tig * 2;
            const float bz0 = bouts[col], bz1 = bouts[col + 1];
#pragma unroll
            for (int mt = 0; mt < 2; ++mt) {
                acc[mt][nt][0] = bz0; acc[mt][nt][1] = bz1;
                acc[mt][nt][2] = bz0; acc[mt][nt][3] = bz1;
            }
        }
        compute_half(xp, wp0, 0, wm, wn, lane, acc);
        compute_half(xp, wp1, 1, wm, wn, lane, acc);

#pragma unroll
        for (int mt = 0; mt < 2; ++mt) {
            const int row = wm * 32 + mt * 16 + g;
#pragma unroll
            for (int nt = 0; nt < 4; ++nt) {
                const int col = wn * 32 + nt * 8 + tig * 2;
                if (row < valid_rows) {
                    float2 v = make_float2(acc[mt][nt][0], acc[mt][nt][1]);
                    *reinterpret_cast<float2*>(&out[(size_t)(row0 + row) * C_CH + col]) = v;
                }
                if (row + 8 < valid_rows) {
                    float2 v = make_float2(acc[mt][nt][2], acc[mt][nt][3]);
                    *reinterpret_cast<float2*>(&out[(size_t)(row0 + row + 8) * C_CH + col]) = v;
                }
            }
        }
    }
}

// ---------------- launch ----------------
extern "C" void kernel_launch(void* const* d_in, const int* in_sizes, int n_in,
                              void* d_out, int out_size) {
    (void)in_sizes; (void)n_in; (void)out_size;
    const float* x     = (const float*)d_in[0];
    const float* gamma = (const float*)d_in[1];
    const float* beta  = (const float*)d_in[2];
    const float* w_qkv = (const float*)d_in[3];
    const float* w_out = (const float*)d_in[4];
    const float* b_out = (const float*)d_in[5];
    const float* mask  = (const float*)d_in[6];
    float* out = (float*)d_out;

    cudaFuncSetAttribute(ga_main_kernel,
                         cudaFuncAttributeMaxDynamicSharedMemorySize,
                         (int)SMEM_TOTAL);

    ga_stats_kernel<<<STATS_BLOCKS, 128>>>(x);
    ga_prep_kernel<<<1, 128>>>(gamma, beta);
    ga_fold_kernel<<<N3 + C_CH, 128>>>(w_qkv, w_out);
    ga_main_kernel<<<GRID_MAIN, THREADS, SMEM_TOTAL>>>(x, b_out, mask, out);
}